// round 9
// baseline (speedup 1.0000x reference)
#include <cuda_runtime.h>
#include <cuda_bf16.h>

#define B 128
#define S 256
#define C 64

__device__ float g_scratch[B];
__device__ int   g_count = 0;

// ---- packed f32x2 helpers (sm_100+; ptxas never auto-fuses) ----
__device__ __forceinline__ unsigned long long f2_mul(unsigned long long a, unsigned long long b) {
    unsigned long long d;
    asm("mul.rn.f32x2 %0, %1, %2;" : "=l"(d) : "l"(a), "l"(b));
    return d;
}
__device__ __forceinline__ unsigned long long f2_fma(unsigned long long a, unsigned long long b, unsigned long long c) {
    unsigned long long d;
    asm("fma.rn.f32x2 %0, %1, %2, %3;" : "=l"(d) : "l"(a), "l"(b), "l"(c));
    return d;
}
__device__ __forceinline__ unsigned long long f2_add(unsigned long long a, unsigned long long b) {
    unsigned long long d;
    asm("add.rn.f32x2 %0, %1, %2;" : "=l"(d) : "l"(a), "l"(b));
    return d;
}
__device__ __forceinline__ float f2_hsum(unsigned long long p) {
    unsigned lo, hi;
    asm("mov.b64 {%0,%1}, %2;" : "=r"(lo), "=r"(hi) : "l"(p));
    return __uint_as_float(lo) + __uint_as_float(hi);
}
__device__ __forceinline__ unsigned long long f2_pack(float x, float y) {
    unsigned long long d;
    asm("mov.b64 %0, {%1,%2};" : "=l"(d) : "f"(x), "f"(y));
    return d;
}

__global__ __launch_bounds__(256, 1) void crf_main(
    const float* __restrict__ emis,   // [B, S, C]
    const int*   __restrict__ tags,   // [B, S]
    const float* __restrict__ mask,   // [B, S]
    const float* __restrict__ U,      // [C, C]
    float*       __restrict__ out)
{
    const int b   = blockIdx.x;
    const int tid = threadIdx.x;
    const int w   = tid >> 5;          // warp 0..7
    const int l   = tid & 31;
    const int qa  = w >> 1;            // i-quarter 0..3 (gather slice, 16 i-values)
    const int jh  = w & 1;             // j-half for partial computation
    const int jo  = jh * 32 + l;       // write-column (partial owner)
    const int c16 = qa * 16 + (l & 15);// rebuild-column (lanes 0..15 active)
    const bool lo16 = (l < 16);

    __shared__ __align__(16) float sh_E[8][16];      // per-warp private e-slice (i-quarter qa)
    __shared__ __align__(16) float sh_p[2][C][4];    // [buf][column][quarter], fully-scaled partials
    __shared__ float sh_r[8], sh_s[2];
    __shared__ int   sh_last;

    const float* embase = emis + (size_t)b * S * C;
    const float* mbase  = mask + b * S;
    const int*   tbase  = tags + b * S;

    // ---------------- path energy partial (1 timestep per thread) ----------------
    float pp;
    int   ok = 1;
    {
        int   s  = tid;
        int   tg = tbase[s];
        float m  = mbase[s];
        int   tm = (int)((float)tg * m);          // matches (tags*mask).astype(int32)
        pp = embase[s * C + tm] * m;
        if (s >= 1) {
            int tp = tbase[s - 1];
            pp += U[tp * C + tg] * m;             // raw tags for transition term
            ok &= (m == 1.f);
        }
    }
    const int allm = __syncthreads_and(ok);       // block-uniform fast-path flag

    // ---------------- exp(U) tile as 8 packed f32x2 pairs ----------------
    unsigned long long u2[8];
#pragma unroll
    for (int k = 0; k < 8; ++k)
        u2[k] = f2_pack(__expf(U[(qa * 16 + 2 * k)     * C + jo]),
                        __expf(U[(qa * 16 + 2 * k + 1) * C + jo]));

    // ---------------- init: private e-slice = exp(alpha_0) on quarter qa ----------------
    if (lo16) sh_E[w][l & 15] = __expf(embase[c16]);

    float base = 0.f;     // cumulative log-shift (uniform)
    float rstale = 1.f;   // stale normalizer: 1/s00 of previous step (uniform)
    int   pb   = 0;

    if (allm) {
        // ======== fast loop: mask==1 everywhere ========
        float e0 = __expf(embase[1 * C + jo]), e1 = __expf(embase[2 * C + jo]);
        float e2 = __expf(embase[3 * C + jo]), e3 = __expf(embase[4 * C + jo]);

        auto stepf = [&](float eem) {
            float em_r = eem * rstale;                     // off-chain (ILP with FMA tree)
            __syncwarp();                                  // order e-writes vs gather reads
            const ulonglong2* ev = (const ulonglong2*)sh_E[w];  // 16 floats = 4x16B, broadcast
            ulonglong2 v0 = ev[0], v1 = ev[1];
            unsigned long long a0 = f2_mul(v0.x, u2[0]);
            unsigned long long a1 = f2_mul(v0.y, u2[1]);
            a0 = f2_fma(v1.x, u2[2], a0);
            a1 = f2_fma(v1.y, u2[3], a1);
            v0 = ev[2]; v1 = ev[3];
            a0 = f2_fma(v0.x, u2[4], a0);
            a1 = f2_fma(v0.y, u2[5], a1);
            a0 = f2_fma(v1.x, u2[6], a0);
            a1 = f2_fma(v1.y, u2[7], a1);
            float part = f2_hsum(f2_add(a0, a1)) * em_r;   // eem*rstale folded pre-bar
            sh_p[pb][jo][qa] = part;
            __syncthreads();                               // ONE block bar per step
            // on-chain combine: pure LDS.128 + adds + STS (no mul)
            if (lo16) {
                float4 pc = *(const float4*)sh_p[pb][c16];
                sh_E[w][l & 15] = (pc.x + pc.y) + (pc.z + pc.w);
            }
            // off-chain (needed next step): stale-normalizer update
            float4 p0 = *(const float4*)sh_p[pb][0];
            float  s00 = (p0.x + p0.y) + (p0.z + p0.w);
            base  += __logf(s00);
            rstale = __fdividef(1.f, s00);
            pb ^= 1;
        };

        for (int t0 = 1; t0 + 3 < S; t0 += 4) {            // t = 1..252
            stepf(e0); e0 = __expf(embase[min(t0 + 4, S - 1) * C + jo]);
            stepf(e1); e1 = __expf(embase[min(t0 + 5, S - 1) * C + jo]);
            stepf(e2); e2 = __expf(embase[min(t0 + 6, S - 1) * C + jo]);
            stepf(e3); e3 = __expf(embase[min(t0 + 7, S - 1) * C + jo]);
        }
        stepf(e0); stepf(e1); stepf(e2);                   // t = 253,254,255
    } else {
        // ======== general loop: per-step mask in {0,1} (same invariant as fast path) ========
        for (int t = 1; t < S; ++t) {
            float m   = mbase[t];
            float eem = __expf(embase[t * C + jo]);
            float em_r = ((m != 0.f) ? eem : 1.f) * rstale;
            __syncwarp();
            float part;
            if (m != 0.f) {
                const ulonglong2* ev = (const ulonglong2*)sh_E[w];
                ulonglong2 v0 = ev[0], v1 = ev[1];
                unsigned long long a0 = f2_mul(v0.x, u2[0]);
                unsigned long long a1 = f2_mul(v0.y, u2[1]);
                a0 = f2_fma(v1.x, u2[2], a0);
                a1 = f2_fma(v1.y, u2[3], a1);
                v0 = ev[2]; v1 = ev[3];
                a0 = f2_fma(v0.x, u2[4], a0);
                a1 = f2_fma(v0.y, u2[5], a1);
                a0 = f2_fma(v1.x, u2[6], a0);
                a1 = f2_fma(v1.y, u2[7], a1);
                part = f2_hsum(f2_add(a0, a1)) * em_r;
            } else {
                float s = 0.f;                             // masked: alpha_new_j = logsumexp_i(alpha_i)
#pragma unroll
                for (int k = 0; k < 16; ++k) s += sh_E[w][k];
                part = s * em_r;                           // no eem on masked steps
            }
            sh_p[pb][jo][qa] = part;
            __syncthreads();
            if (lo16) {
                float4 pc = *(const float4*)sh_p[pb][c16];
                sh_E[w][l & 15] = (pc.x + pc.y) + (pc.z + pc.w);
            }
            float4 p0 = *(const float4*)sh_p[pb][0];
            float  s00 = (p0.x + p0.y) + (p0.z + p0.w);
            base  += __logf(s00);
            rstale = __fdividef(1.f, s00);
            pb ^= 1;
        }
    }
    __syncthreads();

    // ---------------- finalize ----------------
    // Invariant: stored(t) = true(t) * K(t), K(t) = prod_{u=1..t-1} 1/s00(u).
    // base = sum_{t=1..255} log s00(t)  =>  free = log(sum stored) + base - log s00(255)
    //                                            = log(sum stored) + base + log(rstale_final).
    float corr = __logf(rstale);
    float fv = 0.f;
    if (tid < C) {                                   // e lives in jh=0 warps' slices
        int qq = tid >> 4;
        fv = sh_E[2 * qq][tid & 15];
    }
#pragma unroll
    for (int o = 16; o > 0; o >>= 1) {
        fv += __shfl_xor_sync(0xFFFFFFFFu, fv, o);
        pp += __shfl_xor_sync(0xFFFFFFFFu, pp, o);
    }
    if (l == 0) { sh_r[w] = pp; if (w < 2) sh_s[w] = fv; }
    __syncthreads();

    if (tid == 0) {
        float freeE = __logf(sh_s[0] + sh_s[1]) + base + corr;
        float pathE = 0.f;
#pragma unroll
        for (int k = 0; k < 8; ++k) pathE += sh_r[k];
        g_scratch[b] = freeE - pathE;
        __threadfence();
        sh_last = (atomicAdd(&g_count, 1) == B - 1) ? 1 : 0;
    }
    __syncthreads();

    // ---------------- last block: reduce all batches, write mean, reset counter ----------------
    if (sh_last) {
        float v = (tid < B) ? g_scratch[tid] : 0.f;
#pragma unroll
        for (int o = 16; o > 0; o >>= 1)
            v += __shfl_xor_sync(0xFFFFFFFFu, v, o);
        if (l == 0) sh_r[w] = v;
        __syncthreads();
        if (tid == 0) {
            float s = 0.f;
#pragma unroll
            for (int k = 0; k < 8; ++k) s += sh_r[k];
            out[0] = s * (1.f / (float)B);
            g_count = 0;                             // replay-safe reset
        }
    }
}

extern "C" void kernel_launch(void* const* d_in, const int* in_sizes, int n_in,
                              void* d_out, int out_size)
{
    const float* emis = (const float*)d_in[0];
    const int*   tags = (const int*)d_in[1];
    const float* mask = (const float*)d_in[2];
    const float* U    = (const float*)d_in[3];

    crf_main<<<B, 256>>>(emis, tags, mask, U, (float*)d_out);
}